// round 5
// baseline (speedup 1.0000x reference)
#include <cuda_runtime.h>
#include <math.h>

// ---------------------------------------------------------------------------
// DOSAConLoss — single-launch, barrier-free warp-granular version.
//
// loss_loc factorizes (reference broadcasts (N,1)/(N,) -> (N,N) mean):
//   loss_loc = (Sum_i dw_i*hw_i*(1-ciou_i)^2.5) * (Sum_j 1/(area_j+1e-7)) / N^2
//
// One warp handles 32 boxes (1/lane) AND one pair (if gw < P). Warp-level
// shuffle reduce -> RED.ADD.F32 into 3 global scalars. A per-warp acq_rel
// counter elects the last warp, whose lane 0 finalizes and resets state
// (graph-replayable). No __syncthreads anywhere.
// ---------------------------------------------------------------------------

#define EPSF        1e-7f
#define ALPHA_C     1.2f
#define TAU_C       0.3f
#define DELTA_C     1.0f
#define FOUR_PI2    0.40528473456935108577f   // 4/pi^2

#define TPB           512
#define WARPS_PER_BLK (TPB / 32)

__device__ float g_accA = 0.0f;        // Σ dw*hw*(1-ciou)^2.5
__device__ float g_accB = 0.0f;        // Σ 1/(area+1e-7)
__device__ float g_accC = 0.0f;        // Σ masked pair loss
__device__ unsigned int g_done = 0;    // warp completion counter

__device__ __forceinline__ unsigned int atomic_inc_acq_rel(unsigned int* p) {
    unsigned int prev;
    asm volatile("atom.acq_rel.gpu.add.u32 %0, [%1], 1;"
                 : "=r"(prev) : "l"(p) : "memory");
    return prev;
}

__device__ __forceinline__ float ld_acquire_f(const float* p) {
    float v;
    asm volatile("ld.acquire.gpu.f32 %0, [%1];" : "=f"(v) : "l"(p) : "memory");
    return v;
}

__global__ __launch_bounds__(TPB)
void dosa_warp_kernel(const float4* __restrict__ pred,
                      const float4* __restrict__ tgt,
                      const float*  __restrict__ emb,
                      const float*  __restrict__ dens,
                      const int2*   __restrict__ idx,
                      float* __restrict__ out,
                      int N, int D, int P, int totalWarps,
                      float invN2, float pairScale) {
    int lane = threadIdx.x & 31;
    int gw   = blockIdx.x * WARPS_PER_BLK + (threadIdx.x >> 5);

    // ---- issue pair index load FIRST (longest dependent chain) ----
    bool isPair = (gw < P);
    int2 ij = make_int2(0, 0);
    if (isPair) ij = idx[gw];

    // ---- localization: one box per lane (independent of ij; hides latency)
    float accA = 0.0f, accB = 0.0f;
    int i = gw * 32 + lane;
    if (i < N) {
        float4 b1 = pred[i];
        float4 b2 = tgt[i];
        float dv  = dens[i];

        float w1 = b1.z, h1 = b1.w, w2 = b2.z, h2 = b2.w;
        float b1x1 = b1.x - w1 * 0.5f, b1x2 = b1.x + w1 * 0.5f;
        float b1y1 = b1.y - h1 * 0.5f, b1y2 = b1.y + h1 * 0.5f;
        float b2x1 = b2.x - w2 * 0.5f, b2x2 = b2.x + w2 * 0.5f;
        float b2y1 = b2.y - h2 * 0.5f, b2y2 = b2.y + h2 * 0.5f;

        float iw = fmaxf(fminf(b1x2, b2x2) - fmaxf(b1x1, b2x1), 0.0f);
        float ih = fmaxf(fminf(b1y2, b2y2) - fmaxf(b1y1, b2y1), 0.0f);
        float inter = iw * ih;
        float uni   = w1 * h1 + w2 * h2 - inter + EPSF;
        float iou   = __fdividef(inter, uni);

        float cw = fmaxf(b1x2, b2x2) - fminf(b1x1, b2x1);
        float ch = fmaxf(b1y2, b2y2) - fminf(b1y1, b2y1);
        float c2 = cw * cw + ch * ch + EPSF;

        float dx = b2x1 + b2x2 - b1x1 - b1x2;
        float dy = b2y1 + b2y2 - b1y1 - b1y2;
        float rho2 = (dx * dx + dy * dy) * 0.25f;

        float dat = atanf(__fdividef(w2, h2)) - atanf(__fdividef(w1, h1));
        float v   = FOUR_PI2 * dat * dat;
        float alpha = __fdividef(v, v - iou + (1.0f + EPSF));
        float ciou = iou - (__fdividef(rho2, c2) + v * alpha);

        float t  = 1.0f - ciou;                   // >= 0
        float pw = t * t * sqrtf(t);              // t^2.5
        float dw = fmaf(ALPHA_C, dv, 1.0f);
        float hw = __fdividef(1.0f, 1.0f + __expf(-5.0f * (0.5f - ciou)));
        accA = dw * hw * pw;
        accB = __fdividef(1.0f, w2 * h2 + 1e-7f);
    }

    // ---- warp reduce loc partials, post to global accumulators ----
    #pragma unroll
    for (int off = 16; off > 0; off >>= 1) {
        accA += __shfl_down_sync(0xffffffffu, accA, off);
        accB += __shfl_down_sync(0xffffffffu, accB, off);
    }
    if (lane == 0 && accA != 0.0f) {              // always true for valid warps
        atomicAdd(&g_accA, accA);                 // RED.ADD (result unused)
        atomicAdd(&g_accB, accB);
    }

    // ---- pair term (idx arrived during loc math) ----
    if (isPair) {
        int pi = ij.x, pj = ij.y;
        float4 bi = pred[pi];
        float4 bj = pred[pj];
        const float4* ei = (const float4*)(emb + (size_t)pi * D);
        const float4* ej = (const float4*)(emb + (size_t)pj * D);
        int D4 = D >> 2;
        float s = 0.0f;
        for (int c = lane; c < D4; c += 32) {
            float4 u = ei[c];
            float4 v = ej[c];
            float d0 = u.x - v.x, d1 = u.y - v.y;
            float d2 = u.z - v.z, d3 = u.w - v.w;
            s = fmaf(d0, d0, s); s = fmaf(d1, d1, s);
            s = fmaf(d2, d2, s); s = fmaf(d3, d3, s);
        }
        #pragma unroll
        for (int off = 16; off > 0; off >>= 1)
            s += __shfl_down_sync(0xffffffffu, s, off);

        float a_x1 = bi.x - bi.z * 0.5f, a_x2 = bi.x + bi.z * 0.5f;
        float a_y1 = bi.y - bi.w * 0.5f, a_y2 = bi.y + bi.w * 0.5f;
        float b_x1 = bj.x - bj.z * 0.5f, b_x2 = bj.x + bj.z * 0.5f;
        float b_y1 = bj.y - bj.w * 0.5f, b_y2 = bj.y + bj.w * 0.5f;
        float iw = fmaxf(fminf(a_x2, b_x2) - fmaxf(a_x1, b_x1), 0.0f);
        float ih = fmaxf(fminf(a_y2, b_y2) - fmaxf(a_y1, b_y1), 0.0f);
        float inter = iw * ih;
        float uni = bi.z * bi.w + bj.z * bj.w - inter + EPSF;
        float piou = __fdividef(inter, uni);

        if (lane == 0 && piou > TAU_C) {
            float d = sqrtf(s);
            float t = fmaxf(DELTA_C - d, 0.0f);
            if (t > 0.0f) atomicAdd(&g_accC, t * t);
        }
    }

    // ---- last-warp finalize (release via acq_rel counter) ----
    int last = 0;
    if (lane == 0) {
        unsigned int prev = atomic_inc_acq_rel(&g_done);
        last = (prev == (unsigned int)(totalWarps - 1));
    }
    last = __shfl_sync(0xffffffffu, last, 0);
    if (!last) return;

    if (lane == 0) {
        float a = ld_acquire_f(&g_accA);
        float b = ld_acquire_f(&g_accB);
        float c = ld_acquire_f(&g_accC);
        out[0] = a * b * invN2 + c * pairScale;
        // reset for next graph replay (kernel boundary orders visibility)
        g_accA = 0.0f;
        g_accB = 0.0f;
        g_accC = 0.0f;
        g_done = 0;
    }
}

extern "C" void kernel_launch(void* const* d_in, const int* in_sizes, int n_in,
                              void* d_out, int out_size) {
    const float4* pred = (const float4*)d_in[0];
    const float4* tgt  = (const float4*)d_in[1];
    const float*  emb  = (const float*)d_in[2];
    const float*  dens = (const float*)d_in[3];
    const int2*   idx  = (const int2*)d_in[4];
    float* out = (float*)d_out;

    int N = in_sizes[0] / 4;
    int D = in_sizes[2] / N;
    int P = in_sizes[4] / 2;

    int warpsForLoc = (N + 31) / 32;              // 256
    int warpsNeeded = warpsForLoc > P ? warpsForLoc : P;
    int blocks = (warpsNeeded + WARPS_PER_BLK - 1) / WARPS_PER_BLK;  // 16
    int totalWarps = blocks * WARPS_PER_BLK;

    float invN2 = 1.0f / ((float)N * (float)N);
    float pairScale = 0.5f / ((float)P + 1e-7f);

    dosa_warp_kernel<<<blocks, TPB>>>(pred, tgt, emb, dens, idx, out,
                                      N, D, P, totalWarps, invN2, pairScale);
}